// round 13
// baseline (speedup 1.0000x reference)
#include <cuda_runtime.h>
#include <cstdint>
#include <math.h>

// ---------------- problem constants ----------------
#define NROWS 65536
#define DIN   512
#define HID   2048
#define DOUT  512
#define S_IN   0.04419417382415922f   // 1/sqrt(512)
#define S_H2   4.8828125e-4f          // (1/sqrt(2048))^2
#define INV128 0.0078125f
#define INV127 0.007874015748031496f
#define INV127SQ 6.200012400024800e-5f  // (1/127)^2

// ---------------- scratch (static __device__, allowed) ----------------
__device__ __align__(256) int8_t g_Xq0[(size_t)NROWS * DIN];
__device__ __align__(256) int8_t g_Xq1[(size_t)NROWS * DIN];
__device__ float g_sX[NROWS];
__device__ __align__(256) int8_t g_W1q0[(size_t)HID * DIN];   // W1^T [H][DIN]
__device__ __align__(256) int8_t g_W1q1[(size_t)HID * DIN];
__device__ __align__(256) int8_t g_W3q0[(size_t)HID * DIN];
__device__ __align__(256) int8_t g_W3q1[(size_t)HID * DIN];
__device__ __align__(256) int8_t g_W2q0[(size_t)DOUT * HID];  // W2^T [DOUT][H]
__device__ __align__(256) int8_t g_W2q1[(size_t)DOUT * HID];
__device__ __align__(256) int8_t g_W4q0[(size_t)DOUT * HID];
__device__ __align__(256) int8_t g_W4q1[(size_t)DOUT * HID];
__device__ float g_sW1[HID];
__device__ float g_sW3[HID];
__device__ float g_sW2[DOUT];
__device__ float g_sW4[DOUT];
__device__ __align__(256) int8_t g_H1q0[(size_t)NROWS * HID];
__device__ __align__(256) int8_t g_H1q1[(size_t)NROWS * HID];
__device__ __align__(256) int8_t g_H2q0[(size_t)NROWS * HID];
__device__ __align__(256) int8_t g_H2q1[(size_t)NROWS * HID];
__device__ __align__(256) float g_P1[(size_t)NROWS * DOUT];
__device__ __align__(256) float g_P2[(size_t)NROWS * DOUT];

// ---------------- helpers ----------------
__device__ __forceinline__ uint32_t smem_u32(const void* p) {
    uint32_t a;
    asm("{ .reg .u64 t; cvta.to.shared.u64 t, %1; cvt.u32.u64 %0, t; }" : "=r"(a) : "l"(p));
    return a;
}
__device__ __forceinline__ void cp16(uint32_t d, const void* s) {
    asm volatile("cp.async.cg.shared.global [%0], [%1], 16;" :: "r"(d), "l"(s));
}
#define CP_COMMIT() asm volatile("cp.async.commit_group;" ::: "memory")
#define CP_WAIT1()  asm volatile("cp.async.wait_group 1;" ::: "memory")
#define CP_WAIT0()  asm volatile("cp.async.wait_group 0;" ::: "memory")

__device__ __forceinline__ void ldsm4(uint32_t (&r)[4], uint32_t addr) {
    asm volatile("ldmatrix.sync.aligned.m8n8.x4.shared.b16 {%0,%1,%2,%3}, [%4];"
                 : "=r"(r[0]), "=r"(r[1]), "=r"(r[2]), "=r"(r[3]) : "r"(addr));
}
// int8 MMA: m16n8k32, s8 x s8 -> s32
__device__ __forceinline__ void imma(int (&d)[4], const uint32_t (&a)[4],
                                     uint32_t b0, uint32_t b1) {
    asm volatile(
        "mma.sync.aligned.m16n8k32.row.col.s32.s8.s8.s32 "
        "{%0,%1,%2,%3}, {%4,%5,%6,%7}, {%8,%9}, {%0,%1,%2,%3};"
        : "+r"(d[0]), "+r"(d[1]), "+r"(d[2]), "+r"(d[3])
        : "r"(a[0]), "r"(a[1]), "r"(a[2]), "r"(a[3]), "r"(b0), "r"(b1));
}

#define SWZ64(o) ((o) ^ (((o) >> 3) & 0x30))

// ---------------- L0: quantize X + zero weight scales ----------------
__global__ void quant_x_kernel(const float* __restrict__ x) {
    if (blockIdx.x == 0) {
        for (int i = threadIdx.x; i < HID; i += 256) { g_sW1[i] = 0.f; g_sW3[i] = 0.f; }
        for (int i = threadIdx.x; i < DOUT; i += 256) { g_sW2[i] = 0.f; g_sW4[i] = 0.f; }
    }
    int wrow = blockIdx.x * 8 + (threadIdx.x >> 5);
    int lane = threadIdx.x & 31;
    const float4* xr = (const float4*)(x + (size_t)wrow * DIN);
    float4 v[4];
    float m = 0.f;
#pragma unroll
    for (int i = 0; i < 4; i++) {
        v[i] = xr[lane + i * 32];
        m = fmaxf(m, fmaxf(fmaxf(fabsf(v[i].x), fabsf(v[i].y)),
                           fmaxf(fabsf(v[i].z), fabsf(v[i].w))));
    }
#pragma unroll
    for (int o = 16; o; o >>= 1) m = fmaxf(m, __shfl_xor_sync(0xFFFFFFFFu, m, o));
    m = fmaxf(m, 1e-20f);
    float inv = 127.f / m;
    if (lane == 0) g_sX[wrow] = m * INV127;
#pragma unroll
    for (int i = 0; i < 4; i++) {
        float t0 = v[i].x * inv, t1 = v[i].y * inv, t2 = v[i].z * inv, t3 = v[i].w * inv;
        int a0 = __float2int_rn(t0), a1 = __float2int_rn(t1);
        int a2 = __float2int_rn(t2), a3 = __float2int_rn(t3);
        char4 q0 = make_char4((char)a0, (char)a1, (char)a2, (char)a3);
        char4 q1 = make_char4((char)__float2int_rn((t0 - a0) * 128.f),
                              (char)__float2int_rn((t1 - a1) * 128.f),
                              (char)__float2int_rn((t2 - a2) * 128.f),
                              (char)__float2int_rn((t3 - a3) * 128.f));
        ((char4*)g_Xq0)[(size_t)wrow * (DIN / 4) + lane + i * 32] = q0;
        ((char4*)g_Xq1)[(size_t)wrow * (DIN / 4) + lane + i * 32] = q1;
    }
}

// ---------------- L1/L2: weight column max ----------------
__global__ void wcolmax13_kernel(const float* __restrict__ W1, const float* __restrict__ W3) {
    const float* in = blockIdx.z ? W3 : W1;
    float* sc = blockIdx.z ? g_sW3 : g_sW1;
    int n = blockIdx.x * 256 + threadIdx.x;
    const float* p = in + (size_t)blockIdx.y * (DIN / 8) * HID + n;
    float m = 0.f;
#pragma unroll 8
    for (int k = 0; k < DIN / 8; k++) m = fmaxf(m, fabsf(p[(size_t)k * HID]));
    atomicMax((unsigned int*)&sc[n], __float_as_uint(m));
}
__global__ void wcolmax24_kernel(const float* __restrict__ W2, const float* __restrict__ W4) {
    const float* in = blockIdx.z ? W4 : W2;
    float* sc = blockIdx.z ? g_sW4 : g_sW2;
    int n = blockIdx.x * 256 + threadIdx.x;
    const float* p = in + (size_t)blockIdx.y * (HID / 8) * DOUT + n;
    float m = 0.f;
#pragma unroll 8
    for (int k = 0; k < HID / 8; k++) m = fmaxf(m, fabsf(p[(size_t)k * DOUT]));
    atomicMax((unsigned int*)&sc[n], __float_as_uint(m));
}

// ---------------- L3/L4: transpose-quantize ----------------
__global__ void wquant13_kernel(const float* __restrict__ W1, const float* __restrict__ W3) {
    const float* in = blockIdx.z ? W3 : W1;
    int8_t* q0o = blockIdx.z ? g_W3q0 : g_W1q0;
    int8_t* q1o = blockIdx.z ? g_W3q1 : g_W1q1;
    const float* sc = blockIdx.z ? g_sW3 : g_sW1;
    __shared__ float t[32][33];
    int k0 = blockIdx.x * 32, n0 = blockIdx.y * 32;
    int tx = threadIdx.x, ty = threadIdx.y;
#pragma unroll
    for (int i = 0; i < 4; i++)
        t[ty + i * 8][tx] = in[(size_t)(k0 + ty + i * 8) * HID + n0 + tx];
    __syncthreads();
#pragma unroll
    for (int i = 0; i < 4; i++) {
        int n = n0 + ty + i * 8;
        float inv = 127.f / fmaxf(sc[n], 1e-20f);
        float v = t[tx][ty + i * 8] * inv;
        int a = __float2int_rn(v);
        q0o[(size_t)n * DIN + k0 + tx] = (int8_t)a;
        q1o[(size_t)n * DIN + k0 + tx] = (int8_t)__float2int_rn((v - a) * 128.f);
    }
}
__global__ void wquant24_kernel(const float* __restrict__ W2, const float* __restrict__ W4) {
    const float* in = blockIdx.z ? W4 : W2;
    int8_t* q0o = blockIdx.z ? g_W4q0 : g_W2q0;
    int8_t* q1o = blockIdx.z ? g_W4q1 : g_W2q1;
    const float* sc = blockIdx.z ? g_sW4 : g_sW2;
    __shared__ float t[32][33];
    int k0 = blockIdx.x * 32, n0 = blockIdx.y * 32;
    int tx = threadIdx.x, ty = threadIdx.y;
#pragma unroll
    for (int i = 0; i < 4; i++)
        t[ty + i * 8][tx] = in[(size_t)(k0 + ty + i * 8) * DOUT + n0 + tx];
    __syncthreads();
#pragma unroll
    for (int i = 0; i < 4; i++) {
        int n = n0 + ty + i * 8;
        float inv = 127.f / fmaxf(sc[n], 1e-20f);
        float v = t[tx][ty + i * 8] * inv;
        int a = __float2int_rn(v);
        q0o[(size_t)n * HID + k0 + tx] = (int8_t)a;
        q1o[(size_t)n * HID + k0 + tx] = (int8_t)__float2int_rn((v - a) * 128.f);
    }
}

// dp4a hi-term block: lane accumulates its 32 fragment elements for K range
// [kb, kb+32) of the chunk. Exact integer math == imma path.
#define DP4A_HI_BLOCK(TB_CHAR, KB)                                              \
    do {                                                                        \
        _Pragma("unroll")                                                       \
        for (int k4 = 0; k4 < 8; k4++) {                                        \
            const int koff = (KB) + k4 * 4;                                     \
            int a_[2][2], b_[4][2];                                             \
            _Pragma("unroll")                                                   \
            for (int m_ = 0; m_ < 2; m_++)                                      \
                _Pragma("unroll")                                               \
                for (int h_ = 0; h_ < 2; h_++)                                  \
                    a_[m_][h_] = *(const int*)((TB_CHAR) +                      \
                        SWZ64((warp_m * 32 + m_ * 16 + g4 + h_ * 8) * 64 + koff)); \
            _Pragma("unroll")                                                   \
            for (int nf_ = 0; nf_ < 4; nf_++)                                   \
                _Pragma("unroll")                                               \
                for (int co_ = 0; co_ < 2; co_++)                               \
                    b_[nf_][co_] = *(const int*)((TB_CHAR) + 16384 +            \
                        SWZ64((warp_n * 32 + nf_ * 8 + t4v * 2 + co_) * 64 + koff)); \
            _Pragma("unroll")                                                   \
            for (int m_ = 0; m_ < 2; m_++)                                      \
                _Pragma("unroll")                                               \
                for (int nf_ = 0; nf_ < 4; nf_++)                               \
                    _Pragma("unroll")                                           \
                    for (int h_ = 0; h_ < 2; h_++)                              \
                        _Pragma("unroll")                                       \
                        for (int co_ = 0; co_ < 2; co_++)                       \
                            accH[m_][nf_][h_ * 2 + co_] =                       \
                                __dp4a(a_[m_][h_], b_[nf_][co_],                \
                                       accH[m_][nf_][h_ * 2 + co_]);            \
        }                                                                       \
    } while (0)

// ---------------- stage 1: single-branch int8 GEMM (K=512) + activation ------
// Hybrid: ks=0 hi-term on dp4a (ALU pipe), everything else on tensor pipe.
#define BUF1 24576
#define S1_SMEM (3 * BUF1)
__global__ __launch_bounds__(256, 2) void stage1_kernel(const float* __restrict__ bias) {
    extern __shared__ char smem[];
    const uint32_t sb = smem_u32(smem);
    const int tid = threadIdx.x, wid = tid >> 5, lane = tid & 31;
    const int warp_m = wid & 3, warp_n = wid >> 2;
    const int m0 = blockIdx.y * 128, n0 = blockIdx.x * 64;
    const int z = blockIdx.z;
    const int r_lane = lane & 15;
    const int halfb  = ((lane >> 4) & 1) * 16;
    const int g4 = lane >> 2, t4v = lane & 3;

    const int8_t* srcA0 = g_Xq0 + (size_t)m0 * DIN;
    const int8_t* srcA1 = g_Xq1 + (size_t)m0 * DIN;
    const int8_t* srcB0 = (z ? g_W3q0 : g_W1q0) + (size_t)n0 * DIN;
    const int8_t* srcB1 = (z ? g_W3q1 : g_W1q1) + (size_t)n0 * DIN;
    const float* sw = z ? g_sW3 : g_sW1;

    int accH[2][4][4], accL[2][4][4];
#pragma unroll
    for (int m = 0; m < 2; m++)
#pragma unroll
        for (int nf = 0; nf < 4; nf++)
#pragma unroll
            for (int j = 0; j < 4; j++) { accH[m][nf][j] = 0; accL[m][nf][j] = 0; }

    auto load_chunk = [&](int c, int buf) {
        const int k0 = c * 64;
        const uint32_t bb = sb + (uint32_t)buf * BUF1;
#pragma unroll
        for (int i = 0; i < 2; i++) {
            int s = tid + i * 256;
            int row = s >> 2, v = s & 3;
            uint32_t so = SWZ64(row * 64 + v * 16);
            size_t go = (size_t)row * DIN + k0 + v * 16;
            cp16(bb + so,        srcA0 + go);
            cp16(bb + 8192 + so, srcA1 + go);
        }
        {
            int row = tid >> 2, v = tid & 3;
            uint32_t so = SWZ64(row * 64 + v * 16);
            size_t go = (size_t)row * DIN + k0 + v * 16;
            cp16(bb + 16384 + so, srcB0 + go);
            cp16(bb + 20480 + so, srcB1 + go);
        }
    };

    load_chunk(0, 0); CP_COMMIT();
    load_chunk(1, 1); CP_COMMIT();
    const int NCH = DIN / 64;   // 8
    for (int c = 0; c < NCH; c++) {
        if (c == NCH - 1) { CP_WAIT0(); } else { CP_WAIT1(); }
        __syncthreads();
        if (c + 2 < NCH) { load_chunk(c + 2, (c + 2) % 3); CP_COMMIT(); }

        const uint32_t bb = sb + (uint32_t)((c % 3) * BUF1);
        const char* tbc = smem + (size_t)((c % 3) * BUF1);

        // ks = 0: cross terms on tensor, hi term on dp4a (ALU pipe)
        {
            const int kb = 0;
            uint32_t Aq0[2][4], Aq1[2][4];
#pragma unroll
            for (int m = 0; m < 2; m++) {
                uint32_t off = SWZ64((warp_m * 32 + m * 16 + r_lane) * 64 + kb + halfb);
                ldsm4(Aq0[m], bb + off);
                ldsm4(Aq1[m], bb + 8192 + off);
            }
            uint32_t Bq0[2][4], Bq1[2][4];
#pragma unroll
            for (int nb = 0; nb < 2; nb++) {
                uint32_t offB = SWZ64((warp_n * 32 + nb * 16 + r_lane) * 64 + kb + halfb);
                ldsm4(Bq0[nb], bb + 16384 + offB);
                ldsm4(Bq1[nb], bb + 20480 + offB);
            }
#pragma unroll
            for (int nb = 0; nb < 2; nb++)
#pragma unroll
                for (int e = 0; e < 2; e++) {
                    const int nf = nb * 2 + e;
#pragma unroll
                    for (int m = 0; m < 2; m++) {
                        imma(accL[m][nf], Aq0[m], Bq1[nb][e], Bq1[nb][2 + e]);
                        imma(accL[m][nf], Aq1[m], Bq0[nb][e], Bq0[nb][2 + e]);
                    }
                }
            DP4A_HI_BLOCK(tbc, 0);
        }
        // ks = 1: all three terms on tensor
        {
            const int kb = 32;
            uint32_t Aq0[2][4], Aq1[2][4];
#pragma unroll
            for (int m = 0; m < 2; m++) {
                uint32_t off = SWZ64((warp_m * 32 + m * 16 + r_lane) * 64 + kb + halfb);
                ldsm4(Aq0[m], bb + off);
                ldsm4(Aq1[m], bb + 8192 + off);
            }
            uint32_t Bq0[2][4], Bq1[2][4];
#pragma unroll
            for (int nb = 0; nb < 2; nb++) {
                uint32_t offB = SWZ64((warp_n * 32 + nb * 16 + r_lane) * 64 + kb + halfb);
                ldsm4(Bq0[nb], bb + 16384 + offB);
                ldsm4(Bq1[nb], bb + 20480 + offB);
            }
#pragma unroll
            for (int nb = 0; nb < 2; nb++)
#pragma unroll
                for (int e = 0; e < 2; e++) {
                    const int nf = nb * 2 + e;
#pragma unroll
                    for (int m = 0; m < 2; m++) {
                        imma(accH[m][nf], Aq0[m], Bq0[nb][e], Bq0[nb][2 + e]);
                        imma(accL[m][nf], Aq0[m], Bq1[nb][e], Bq1[nb][2 + e]);
                        imma(accL[m][nf], Aq1[m], Bq0[nb][e], Bq0[nb][2 + e]);
                    }
                }
        }
    }

    // ---- epilogue: dequant, activation, 2-level int8 quant, staged via smem ----
    __syncthreads();
    const int g = lane >> 2, t4 = lane & 3;
    float sx[2][2];
#pragma unroll
    for (int m = 0; m < 2; m++)
#pragma unroll
        for (int h = 0; h < 2; h++)
            sx[m][h] = g_sX[m0 + warp_m * 32 + m * 16 + g + h * 8];

#pragma unroll
    for (int m = 0; m < 2; m++)
#pragma unroll
        for (int nf = 0; nf < 4; nf++) {
            const int cl = warp_n * 32 + nf * 8 + t4 * 2;
            const float swa = sw[n0 + cl] * INV127, swb = sw[n0 + cl + 1] * INV127;
            float ba = 0.f, bb2 = 0.f;
            if (z == 0) { ba = __ldg(bias + n0 + cl); bb2 = __ldg(bias + n0 + cl + 1); }
#pragma unroll
            for (int h = 0; h < 2; h++) {
                const int rl = warp_m * 32 + m * 16 + g + h * 8;
                const float s = sx[m][h];
                float va = s * swa * ((float)accH[m][nf][h * 2 + 0] + INV128 * (float)accL[m][nf][h * 2 + 0]);
                float vb = s * swb * ((float)accH[m][nf][h * 2 + 1] + INV128 * (float)accL[m][nf][h * 2 + 1]);
                float ha, hb;
                if (z == 0) {
                    ha = __cosf(va * S_IN + ba);
                    hb = __cosf(vb * S_IN + bb2);
                } else {
                    ha = 1.f / (1.f + __expf(-va * S_IN));
                    hb = 1.f / (1.f + __expf(-vb * S_IN));
                }
                float ta = ha * 127.f, tb = hb * 127.f;
                int qa = __float2int_rn(ta), qb = __float2int_rn(tb);
                char2 cq0 = make_char2((char)qa, (char)qb);
                char2 cq1 = make_char2((char)__float2int_rn((ta - qa) * 128.f),
                                       (char)__float2int_rn((tb - qb) * 128.f));
                uint32_t off = (uint32_t)rl * 80 + cl;
                *(char2*)(smem + off)         = cq0;
                *(char2*)(smem + 10240 + off) = cq1;
            }
        }
    __syncthreads();

    {
        int8_t* o0 = z ? g_H2q0 : g_H1q0;
        int8_t* o1 = z ? g_H2q1 : g_H1q1;
#pragma unroll
        for (int i = 0; i < 2; i++) {
            int s = tid + i * 256;
            int row = s >> 2, colc = (s & 3) * 16;
            uint32_t so = (uint32_t)row * 80 + colc;
            size_t go = (size_t)(m0 + row) * HID + n0 + colc;
            *(uint4*)(o0 + go) = *(const uint4*)(smem + so);
            *(uint4*)(o1 + go) = *(const uint4*)(smem + 10240 + so);
        }
    }
}

// ---------------- stage 2: single-branch int8 GEMM (K=2048) -> P ----------------
#define BUF2 24576
#define S2_SMEM (3 * BUF2)
__global__ __launch_bounds__(256, 2) void stage2_kernel() {
    extern __shared__ char smem[];
    const uint32_t sb = smem_u32(smem);
    const int tid = threadIdx.x, wid = tid >> 5, lane = tid & 31;
    const int warp_m = wid & 3, warp_n = wid >> 2;
    const int m0 = blockIdx.y * 128, c0 = blockIdx.x * 64;
    const int z = blockIdx.z;
    const int r_lane = lane & 15;
    const int halfb  = ((lane >> 4) & 1) * 16;
    const int g4 = lane >> 2, t4v = lane & 3;

    const int8_t* srcA0 = (z ? g_H2q0 : g_H1q0) + (size_t)m0 * HID;
    const int8_t* srcA1 = (z ? g_H2q1 : g_H1q1) + (size_t)m0 * HID;
    const int8_t* srcB0 = (z ? g_W4q0 : g_W2q0) + (size_t)c0 * HID;
    const int8_t* srcB1 = (z ? g_W4q1 : g_W2q1) + (size_t)c0 * HID;
    const float* sw = z ? g_sW4 : g_sW2;
    float* P = z ? g_P2 : g_P1;

    int accH[2][4][4], accL[2][4][4];
#pragma unroll
    for (int m = 0; m < 2; m++)
#pragma unroll
        for (int nf = 0; nf < 4; nf++)
#pragma unroll
            for (int j = 0; j < 4; j++) { accH[m][nf][j] = 0; accL[m][nf][j] = 0; }

    auto load_chunk = [&](int c, int buf) {
        const int k0 = c * 64;
        const uint32_t bb = sb + (uint32_t)buf * BUF2;
#pragma unroll
        for (int i = 0; i < 2; i++) {
            int s = tid + i * 256;
            int row = s >> 2, v = s & 3;
            uint32_t so = SWZ64(row * 64 + v * 16);
            size_t go = (size_t)row * HID + k0 + v * 16;
            cp16(bb + so,        srcA0 + go);
            cp16(bb + 8192 + so, srcA1 + go);
        }
        {
            int row = tid >> 2, v = tid & 3;
            uint32_t so = SWZ64(row * 64 + v * 16);
            size_t go = (size_t)row * HID + k0 + v * 16;
            cp16(bb + 16384 + so, srcB0 + go);
            cp16(bb + 20480 + so, srcB1 + go);
        }
    };

    load_chunk(0, 0); CP_COMMIT();
    load_chunk(1, 1); CP_COMMIT();
    const int NCH = HID / 64;   // 32
    for (int c = 0; c < NCH; c++) {
        if (c == NCH - 1) { CP_WAIT0(); } else { CP_WAIT1(); }
        __syncthreads();
        if (c + 2 < NCH) { load_chunk(c + 2, (c + 2) % 3); CP_COMMIT(); }

        const uint32_t bb = sb + (uint32_t)((c % 3) * BUF2);
        const char* tbc = smem + (size_t)((c % 3) * BUF2);

        // ks = 0: cross on tensor, hi on dp4a
        {
            const int kb = 0;
            uint32_t Aq0[2][4], Aq1[2][4];
#pragma unroll
            for (int m = 0; m < 2; m++) {
                uint32_t off = SWZ64((warp_m * 32 + m * 16 + r_lane) * 64 + kb + halfb);
                ldsm4(Aq0[m], bb + off);
                ldsm4(Aq1[m], bb + 8192 + off);
            }
            uint32_t Bq0[2][4], Bq1[2][4];
#pragma unroll
            for (int nb = 0; nb < 2; nb++) {
                uint32_t offB = SWZ64((warp_n * 32 + nb * 16 + r_lane) * 64 + kb + halfb);
                ldsm4(Bq0[nb], bb + 16384 + offB);
                ldsm4(Bq1[nb], bb + 20480 + offB);
            }
#pragma unroll
            for (int nb = 0; nb < 2; nb++)
#pragma unroll
                for (int e = 0; e < 2; e++) {
                    const int nf = nb * 2 + e;
#pragma unroll
                    for (int m = 0; m < 2; m++) {
                        imma(accL[m][nf], Aq0[m], Bq1[nb][e], Bq1[nb][2 + e]);
                        imma(accL[m][nf], Aq1[m], Bq0[nb][e], Bq0[nb][2 + e]);
                    }
                }
            DP4A_HI_BLOCK(tbc, 0);
        }
        // ks = 1: all on tensor
        {
            const int kb = 32;
            uint32_t Aq0[2][4], Aq1[2][4];
#pragma unroll
            for (int m = 0; m < 2; m++) {
                uint32_t off = SWZ64((warp_m * 32 + m * 16 + r_lane) * 64 + kb + halfb);
                ldsm4(Aq0[m], bb + off);
                ldsm4(Aq1[m], bb + 8192 + off);
            }
            uint32_t Bq0[2][4], Bq1[2][4];
#pragma unroll
            for (int nb = 0; nb < 2; nb++) {
                uint32_t offB = SWZ64((warp_n * 32 + nb * 16 + r_lane) * 64 + kb + halfb);
                ldsm4(Bq0[nb], bb + 16384 + offB);
                ldsm4(Bq1[nb], bb + 20480 + offB);
            }
#pragma unroll
            for (int nb = 0; nb < 2; nb++)
#pragma unroll
                for (int e = 0; e < 2; e++) {
                    const int nf = nb * 2 + e;
#pragma unroll
                    for (int m = 0; m < 2; m++) {
                        imma(accH[m][nf], Aq0[m], Bq0[nb][e], Bq0[nb][2 + e]);
                        imma(accL[m][nf], Aq0[m], Bq1[nb][e], Bq1[nb][2 + e]);
                        imma(accL[m][nf], Aq1[m], Bq0[nb][e], Bq0[nb][2 + e]);
                    }
                }
        }
    }

    // epilogue: P = dequantized GEMM value (pre-s_h)
    const int g = lane >> 2, t4 = lane & 3;
#pragma unroll
    for (int m = 0; m < 2; m++)
#pragma unroll
        for (int nf = 0; nf < 4; nf++) {
            const int cl = warp_n * 32 + nf * 8 + t4 * 2;
            const float swa = sw[c0 + cl] * INV127SQ, swb = sw[c0 + cl + 1] * INV127SQ;
#pragma unroll
            for (int h = 0; h < 2; h++) {
                const int row = m0 + warp_m * 32 + m * 16 + g + h * 8;
                float2 o;
                o.x = swa * ((float)accH[m][nf][h * 2 + 0] + INV128 * (float)accL[m][nf][h * 2 + 0]);
                o.y = swb * ((float)accH[m][nf][h * 2 + 1] + INV128 * (float)accL[m][nf][h * 2 + 1]);
                *(float2*)(P + (size_t)row * DOUT + c0 + cl) = o;
            }
        }
}

// ---------------- combine: out = P1*P2*S_H2 ----------------
__global__ void combine_kernel(float* __restrict__ out) {
    size_t i = (size_t)blockIdx.x * 256 + threadIdx.x;
    float4 a = ((const float4*)g_P1)[i];
    float4 b = ((const float4*)g_P2)[i];
    float4 o;
    o.x = a.x * b.x * S_H2;
    o.y = a.y * b.y * S_H2;
    o.z = a.z * b.z * S_H2;
    o.w = a.w * b.w * S_H2;
    ((float4*)out)[i] = o;
}

// ---------------- launch ----------------
// Inputs (metadata order): x, W_rff1, bias, W_rff2, W_sig1, W_sig2
extern "C" void kernel_launch(void* const* d_in, const int* in_sizes, int n_in,
                              void* d_out, int out_size)
{
    (void)in_sizes; (void)n_in; (void)out_size;
    const float* x    = (const float*)d_in[0];
    const float* W1   = (const float*)d_in[1];
    const float* bias = (const float*)d_in[2];
    const float* W2   = (const float*)d_in[3];
    const float* W3   = (const float*)d_in[4];
    const float* W4   = (const float*)d_in[5];
    float* out = (float*)d_out;

    cudaFuncSetAttribute(stage1_kernel, cudaFuncAttributeMaxDynamicSharedMemorySize, S1_SMEM);
    cudaFuncSetAttribute(stage2_kernel, cudaFuncAttributeMaxDynamicSharedMemorySize, S2_SMEM);

    quant_x_kernel<<<NROWS / 8, 256>>>(x);
    wcolmax13_kernel<<<dim3(HID / 256, 8, 2),  256>>>(W1, W3);
    wcolmax24_kernel<<<dim3(DOUT / 256, 8, 2), 256>>>(W2, W4);
    wquant13_kernel<<<dim3(DIN / 32, HID / 32, 2),  dim3(32, 8)>>>(W1, W3);
    wquant24_kernel<<<dim3(HID / 32, DOUT / 32, 2), dim3(32, 8)>>>(W2, W4);
    stage1_kernel<<<dim3(HID / 64, NROWS / 128, 2), 256, S1_SMEM>>>(bias);
    stage2_kernel<<<dim3(DOUT / 64, NROWS / 128, 2), 256, S2_SMEM>>>();
    combine_kernel<<<(NROWS * DOUT / 4) / 256, 256>>>(out);
}

// round 14
// speedup vs baseline: 1.9094x; 1.9094x over previous
#include <cuda_runtime.h>
#include <cstdint>
#include <math.h>

// ---------------- problem constants ----------------
#define NROWS 65536
#define DIN   512
#define HID   2048
#define DOUT  512
#define S_IN   0.04419417382415922f   // 1/sqrt(512)
#define S_H2   4.8828125e-4f          // (1/sqrt(2048))^2
#define INV128 0.0078125f
#define INV127 0.007874015748031496f
#define INV127SQ 6.200012400024800e-5f  // (1/127)^2

// ---------------- scratch (static __device__, allowed) ----------------
__device__ __align__(256) int8_t g_Xq0[(size_t)NROWS * DIN];
__device__ __align__(256) int8_t g_Xq1[(size_t)NROWS * DIN];
__device__ float g_sX[NROWS];
__device__ __align__(256) int8_t g_W1q0[(size_t)HID * DIN];   // W1^T [H][DIN]
__device__ __align__(256) int8_t g_W1q1[(size_t)HID * DIN];
__device__ __align__(256) int8_t g_W3q0[(size_t)HID * DIN];
__device__ __align__(256) int8_t g_W3q1[(size_t)HID * DIN];
__device__ __align__(256) int8_t g_W2q0[(size_t)DOUT * HID];  // W2^T [DOUT][H]
__device__ __align__(256) int8_t g_W2q1[(size_t)DOUT * HID];
__device__ __align__(256) int8_t g_W4q0[(size_t)DOUT * HID];
__device__ __align__(256) int8_t g_W4q1[(size_t)DOUT * HID];
__device__ float g_sW1[HID];
__device__ float g_sW3[HID];
__device__ float g_sW2[DOUT];
__device__ float g_sW4[DOUT];
__device__ __align__(256) int8_t g_H1q0[(size_t)NROWS * HID];
__device__ __align__(256) int8_t g_H1q1[(size_t)NROWS * HID];
__device__ __align__(256) int8_t g_H2q0[(size_t)NROWS * HID];
__device__ __align__(256) int8_t g_H2q1[(size_t)NROWS * HID];
__device__ __align__(256) float g_P1[(size_t)NROWS * DOUT];
__device__ __align__(256) float g_P2[(size_t)NROWS * DOUT];

// ---------------- helpers ----------------
__device__ __forceinline__ uint32_t smem_u32(const void* p) {
    uint32_t a;
    asm("{ .reg .u64 t; cvta.to.shared.u64 t, %1; cvt.u32.u64 %0, t; }" : "=r"(a) : "l"(p));
    return a;
}
__device__ __forceinline__ void cp16(uint32_t d, const void* s) {
    asm volatile("cp.async.cg.shared.global [%0], [%1], 16;" :: "r"(d), "l"(s));
}
#define CP_COMMIT() asm volatile("cp.async.commit_group;" ::: "memory")
#define CP_WAIT1()  asm volatile("cp.async.wait_group 1;" ::: "memory")
#define CP_WAIT0()  asm volatile("cp.async.wait_group 0;" ::: "memory")

__device__ __forceinline__ void ldsm4(uint32_t (&r)[4], uint32_t addr) {
    asm volatile("ldmatrix.sync.aligned.m8n8.x4.shared.b16 {%0,%1,%2,%3}, [%4];"
                 : "=r"(r[0]), "=r"(r[1]), "=r"(r[2]), "=r"(r[3]) : "r"(addr));
}
// int8 MMA: m16n8k32, s8 x s8 -> s32
__device__ __forceinline__ void imma(int (&d)[4], const uint32_t (&a)[4],
                                     uint32_t b0, uint32_t b1) {
    asm volatile(
        "mma.sync.aligned.m16n8k32.row.col.s32.s8.s8.s32 "
        "{%0,%1,%2,%3}, {%4,%5,%6,%7}, {%8,%9}, {%0,%1,%2,%3};"
        : "+r"(d[0]), "+r"(d[1]), "+r"(d[2]), "+r"(d[3])
        : "r"(a[0]), "r"(a[1]), "r"(a[2]), "r"(a[3]), "r"(b0), "r"(b1));
}

#define SWZ64(o) ((o) ^ (((o) >> 3) & 0x30))

// ---------------- L0: quantize X + zero weight scales ----------------
__global__ void quant_x_kernel(const float* __restrict__ x) {
    if (blockIdx.x == 0) {
        for (int i = threadIdx.x; i < HID; i += 256) { g_sW1[i] = 0.f; g_sW3[i] = 0.f; }
        for (int i = threadIdx.x; i < DOUT; i += 256) { g_sW2[i] = 0.f; g_sW4[i] = 0.f; }
    }
    int wrow = blockIdx.x * 8 + (threadIdx.x >> 5);
    int lane = threadIdx.x & 31;
    const float4* xr = (const float4*)(x + (size_t)wrow * DIN);
    float4 v[4];
    float m = 0.f;
#pragma unroll
    for (int i = 0; i < 4; i++) {
        v[i] = xr[lane + i * 32];
        m = fmaxf(m, fmaxf(fmaxf(fabsf(v[i].x), fabsf(v[i].y)),
                           fmaxf(fabsf(v[i].z), fabsf(v[i].w))));
    }
#pragma unroll
    for (int o = 16; o; o >>= 1) m = fmaxf(m, __shfl_xor_sync(0xFFFFFFFFu, m, o));
    m = fmaxf(m, 1e-20f);
    float inv = 127.f / m;
    if (lane == 0) g_sX[wrow] = m * INV127;
#pragma unroll
    for (int i = 0; i < 4; i++) {
        float t0 = v[i].x * inv, t1 = v[i].y * inv, t2 = v[i].z * inv, t3 = v[i].w * inv;
        int a0 = __float2int_rn(t0), a1 = __float2int_rn(t1);
        int a2 = __float2int_rn(t2), a3 = __float2int_rn(t3);
        char4 q0 = make_char4((char)a0, (char)a1, (char)a2, (char)a3);
        char4 q1 = make_char4((char)__float2int_rn((t0 - a0) * 128.f),
                              (char)__float2int_rn((t1 - a1) * 128.f),
                              (char)__float2int_rn((t2 - a2) * 128.f),
                              (char)__float2int_rn((t3 - a3) * 128.f));
        ((char4*)g_Xq0)[(size_t)wrow * (DIN / 4) + lane + i * 32] = q0;
        ((char4*)g_Xq1)[(size_t)wrow * (DIN / 4) + lane + i * 32] = q1;
    }
}

// ---------------- L1/L2: weight column max ----------------
__global__ void wcolmax13_kernel(const float* __restrict__ W1, const float* __restrict__ W3) {
    const float* in = blockIdx.z ? W3 : W1;
    float* sc = blockIdx.z ? g_sW3 : g_sW1;
    int n = blockIdx.x * 256 + threadIdx.x;
    const float* p = in + (size_t)blockIdx.y * (DIN / 8) * HID + n;
    float m = 0.f;
#pragma unroll 8
    for (int k = 0; k < DIN / 8; k++) m = fmaxf(m, fabsf(p[(size_t)k * HID]));
    atomicMax((unsigned int*)&sc[n], __float_as_uint(m));
}
__global__ void wcolmax24_kernel(const float* __restrict__ W2, const float* __restrict__ W4) {
    const float* in = blockIdx.z ? W4 : W2;
    float* sc = blockIdx.z ? g_sW4 : g_sW2;
    int n = blockIdx.x * 256 + threadIdx.x;
    const float* p = in + (size_t)blockIdx.y * (HID / 8) * DOUT + n;
    float m = 0.f;
#pragma unroll 8
    for (int k = 0; k < HID / 8; k++) m = fmaxf(m, fabsf(p[(size_t)k * DOUT]));
    atomicMax((unsigned int*)&sc[n], __float_as_uint(m));
}

// ---------------- L3/L4: transpose-quantize ----------------
__global__ void wquant13_kernel(const float* __restrict__ W1, const float* __restrict__ W3) {
    const float* in = blockIdx.z ? W3 : W1;
    int8_t* q0o = blockIdx.z ? g_W3q0 : g_W1q0;
    int8_t* q1o = blockIdx.z ? g_W3q1 : g_W1q1;
    const float* sc = blockIdx.z ? g_sW3 : g_sW1;
    __shared__ float t[32][33];
    int k0 = blockIdx.x * 32, n0 = blockIdx.y * 32;
    int tx = threadIdx.x, ty = threadIdx.y;
#pragma unroll
    for (int i = 0; i < 4; i++)
        t[ty + i * 8][tx] = in[(size_t)(k0 + ty + i * 8) * HID + n0 + tx];
    __syncthreads();
#pragma unroll
    for (int i = 0; i < 4; i++) {
        int n = n0 + ty + i * 8;
        float inv = 127.f / fmaxf(sc[n], 1e-20f);
        float v = t[tx][ty + i * 8] * inv;
        int a = __float2int_rn(v);
        q0o[(size_t)n * DIN + k0 + tx] = (int8_t)a;
        q1o[(size_t)n * DIN + k0 + tx] = (int8_t)__float2int_rn((v - a) * 128.f);
    }
}
__global__ void wquant24_kernel(const float* __restrict__ W2, const float* __restrict__ W4) {
    const float* in = blockIdx.z ? W4 : W2;
    int8_t* q0o = blockIdx.z ? g_W4q0 : g_W2q0;
    int8_t* q1o = blockIdx.z ? g_W4q1 : g_W2q1;
    const float* sc = blockIdx.z ? g_sW4 : g_sW2;
    __shared__ float t[32][33];
    int k0 = blockIdx.x * 32, n0 = blockIdx.y * 32;
    int tx = threadIdx.x, ty = threadIdx.y;
#pragma unroll
    for (int i = 0; i < 4; i++)
        t[ty + i * 8][tx] = in[(size_t)(k0 + ty + i * 8) * DOUT + n0 + tx];
    __syncthreads();
#pragma unroll
    for (int i = 0; i < 4; i++) {
        int n = n0 + ty + i * 8;
        float inv = 127.f / fmaxf(sc[n], 1e-20f);
        float v = t[tx][ty + i * 8] * inv;
        int a = __float2int_rn(v);
        q0o[(size_t)n * HID + k0 + tx] = (int8_t)a;
        q1o[(size_t)n * HID + k0 + tx] = (int8_t)__float2int_rn((v - a) * 128.f);
    }
}

// ---------------- stage 1: single-branch int8 GEMM (K=512) + activation ------
// 8 warps, warp tile 16x32 (warp_m = wid), CTA tile 128x32, 3 CTAs/SM.
// buffer = Aq0,Aq1 (8KB each) + Bq0,Bq1 (2KB each) = 20KB; 3 buffers = 60KB.
#define BUF1 20480
#define S1_SMEM (3 * BUF1)
__global__ __launch_bounds__(256, 3) void stage1_kernel(const float* __restrict__ bias) {
    extern __shared__ char smem[];
    const uint32_t sb = smem_u32(smem);
    const int tid = threadIdx.x, wid = tid >> 5, lane = tid & 31;
    const int warp_m = wid;                 // 0..7, 16 rows each
    const int m0 = blockIdx.y * 128, n0 = blockIdx.x * 32;
    const int z = blockIdx.z;
    const int r_lane = lane & 15;
    const int halfb  = ((lane >> 4) & 1) * 16;

    const int8_t* srcA0 = g_Xq0 + (size_t)m0 * DIN;
    const int8_t* srcA1 = g_Xq1 + (size_t)m0 * DIN;
    const int8_t* srcB0 = (z ? g_W3q0 : g_W1q0) + (size_t)n0 * DIN;
    const int8_t* srcB1 = (z ? g_W3q1 : g_W1q1) + (size_t)n0 * DIN;
    const float* sw = z ? g_sW3 : g_sW1;

    int accH[4][4], accL[4][4];
#pragma unroll
    for (int nf = 0; nf < 4; nf++)
#pragma unroll
        for (int j = 0; j < 4; j++) { accH[nf][j] = 0; accL[nf][j] = 0; }

    auto load_chunk = [&](int c, int buf) {
        const int k0 = c * 64;
        const uint32_t bb = sb + (uint32_t)buf * BUF1;
#pragma unroll
        for (int i = 0; i < 2; i++) {      // A planes: 512 cp16 each, 2/thread
            int s = tid + i * 256;
            int row = s >> 2, v = s & 3;
            uint32_t so = SWZ64(row * 64 + v * 16);
            size_t go = (size_t)row * DIN + k0 + v * 16;
            cp16(bb + so,        srcA0 + go);
            cp16(bb + 8192 + so, srcA1 + go);
        }
        {   // B planes: 32 rows x 4 slots = 128 cp16 each; 256 threads -> 1 each
            int t = tid >> 7, r = tid & 127;
            int row = r >> 2, v = r & 3;
            uint32_t so = SWZ64(row * 64 + v * 16);
            size_t go = (size_t)row * DIN + k0 + v * 16;
            cp16(bb + 16384 + (uint32_t)t * 2048 + so, (t ? srcB1 : srcB0) + go);
        }
    };

    load_chunk(0, 0); CP_COMMIT();
    load_chunk(1, 1); CP_COMMIT();
    const int NCH = DIN / 64;   // 8
    for (int c = 0; c < NCH; c++) {
        if (c == NCH - 1) { CP_WAIT0(); } else { CP_WAIT1(); }
        __syncthreads();
        if (c + 2 < NCH) { load_chunk(c + 2, (c + 2) % 3); CP_COMMIT(); }

        const uint32_t bb = sb + (uint32_t)((c % 3) * BUF1);
#pragma unroll
        for (int ks = 0; ks < 2; ks++) {
            const int kb = ks * 32;
            uint32_t Aq0[4], Aq1[4];
            {
                uint32_t off = SWZ64((warp_m * 16 + r_lane) * 64 + kb + halfb);
                ldsm4(Aq0, bb + off);
                ldsm4(Aq1, bb + 8192 + off);
            }
            uint32_t Bq0[2][4], Bq1[2][4];
#pragma unroll
            for (int nb = 0; nb < 2; nb++) {
                uint32_t offB = SWZ64((nb * 16 + r_lane) * 64 + kb + halfb);
                ldsm4(Bq0[nb], bb + 16384 + offB);
                ldsm4(Bq1[nb], bb + 18432 + offB);
            }
#pragma unroll
            for (int nb = 0; nb < 2; nb++)
#pragma unroll
                for (int e = 0; e < 2; e++) {
                    const int nf = nb * 2 + e;
                    imma(accH[nf], Aq0, Bq0[nb][e], Bq0[nb][2 + e]);
                    imma(accL[nf], Aq0, Bq1[nb][e], Bq1[nb][2 + e]);
                    imma(accL[nf], Aq1, Bq0[nb][e], Bq0[nb][2 + e]);
                }
        }
    }

    // ---- epilogue: dequant, activation, 2-level int8 quant, staged via smem ----
    __syncthreads();
    const int g = lane >> 2, t4 = lane & 3;
    float sx[2];
#pragma unroll
    for (int h = 0; h < 2; h++)
        sx[h] = g_sX[m0 + warp_m * 16 + g + h * 8];

#pragma unroll
    for (int nf = 0; nf < 4; nf++) {
        const int cl = nf * 8 + t4 * 2;
        const float swa = sw[n0 + cl] * INV127, swb = sw[n0 + cl + 1] * INV127;
        float ba = 0.f, bb2 = 0.f;
        if (z == 0) { ba = __ldg(bias + n0 + cl); bb2 = __ldg(bias + n0 + cl + 1); }
#pragma unroll
        for (int h = 0; h < 2; h++) {
            const int rl = warp_m * 16 + g + h * 8;
            const float s = sx[h];
            float va = s * swa * ((float)accH[nf][h * 2 + 0] + INV128 * (float)accL[nf][h * 2 + 0]);
            float vb = s * swb * ((float)accH[nf][h * 2 + 1] + INV128 * (float)accL[nf][h * 2 + 1]);
            float ha, hb;
            if (z == 0) {
                ha = __cosf(va * S_IN + ba);
                hb = __cosf(vb * S_IN + bb2);
            } else {
                ha = 1.f / (1.f + __expf(-va * S_IN));
                hb = 1.f / (1.f + __expf(-vb * S_IN));
            }
            float ta = ha * 127.f, tb = hb * 127.f;
            int qa = __float2int_rn(ta), qb = __float2int_rn(tb);
            char2 cq0 = make_char2((char)qa, (char)qb);
            char2 cq1 = make_char2((char)__float2int_rn((ta - qa) * 128.f),
                                   (char)__float2int_rn((tb - qb) * 128.f));
            uint32_t off = (uint32_t)rl * 48 + cl;      // 128 x (32+16 pad) staging
            *(char2*)(smem + off)        = cq0;
            *(char2*)(smem + 6144 + off) = cq1;
        }
    }
    __syncthreads();

    {   // coalesced store: 2 planes of 128x32, 16B per thread
        int8_t* o0 = z ? g_H2q0 : g_H1q0;
        int8_t* o1 = z ? g_H2q1 : g_H1q1;
        int row = tid >> 1, colc = (tid & 1) * 16;
        uint32_t so = (uint32_t)row * 48 + colc;
        size_t go = (size_t)(m0 + row) * HID + n0 + colc;
        *(uint4*)(o0 + go) = *(const uint4*)(smem + so);
        *(uint4*)(o1 + go) = *(const uint4*)(smem + 6144 + so);
    }
}

// ---------------- stage 2: single-branch int8 GEMM (K=2048) -> P ----------------
// grid (DOUT/32=16, 512, 2), CTA tile 128x32, 3 CTAs/SM.
#define BUF2 20480
#define S2_SMEM (3 * BUF2)
__global__ __launch_bounds__(256, 3) void stage2_kernel() {
    extern __shared__ char smem[];
    const uint32_t sb = smem_u32(smem);
    const int tid = threadIdx.x, wid = tid >> 5, lane = tid & 31;
    const int warp_m = wid;
    const int m0 = blockIdx.y * 128, c0 = blockIdx.x * 32;
    const int z = blockIdx.z;
    const int r_lane = lane & 15;
    const int halfb  = ((lane >> 4) & 1) * 16;

    const int8_t* srcA0 = (z ? g_H2q0 : g_H1q0) + (size_t)m0 * HID;
    const int8_t* srcA1 = (z ? g_H2q1 : g_H1q1) + (size_t)m0 * HID;
    const int8_t* srcB0 = (z ? g_W4q0 : g_W2q0) + (size_t)c0 * HID;
    const int8_t* srcB1 = (z ? g_W4q1 : g_W2q1) + (size_t)c0 * HID;
    const float* sw = z ? g_sW4 : g_sW2;
    float* P = z ? g_P2 : g_P1;

    int accH[4][4], accL[4][4];
#pragma unroll
    for (int nf = 0; nf < 4; nf++)
#pragma unroll
        for (int j = 0; j < 4; j++) { accH[nf][j] = 0; accL[nf][j] = 0; }

    auto load_chunk = [&](int c, int buf) {
        const int k0 = c * 64;
        const uint32_t bb = sb + (uint32_t)buf * BUF2;
#pragma unroll
        for (int i = 0; i < 2; i++) {
            int s = tid + i * 256;
            int row = s >> 2, v = s & 3;
            uint32_t so = SWZ64(row * 64 + v * 16);
            size_t go = (size_t)row * HID + k0 + v * 16;
            cp16(bb + so,        srcA0 + go);
            cp16(bb + 8192 + so, srcA1 + go);
        }
        {
            int t = tid >> 7, r = tid & 127;
            int row = r >> 2, v = r & 3;
            uint32_t so = SWZ64(row * 64 + v * 16);
            size_t go = (size_t)row * HID + k0 + v * 16;
            cp16(bb + 16384 + (uint32_t)t * 2048 + so, (t ? srcB1 : srcB0) + go);
        }
    };

    load_chunk(0, 0); CP_COMMIT();
    load_chunk(1, 1); CP_COMMIT();
    const int NCH = HID / 64;   // 32
    for (int c = 0; c < NCH; c++) {
        if (c == NCH - 1) { CP_WAIT0(); } else { CP_WAIT1(); }
        __syncthreads();
        if (c + 2 < NCH) { load_chunk(c + 2, (c + 2) % 3); CP_COMMIT(); }

        const uint32_t bb = sb + (uint32_t)((c % 3) * BUF2);
#pragma unroll
        for (int ks = 0; ks < 2; ks++) {
            const int kb = ks * 32;
            uint32_t Aq0[4], Aq1[4];
            {
                uint32_t off = SWZ64((warp_m * 16 + r_lane) * 64 + kb + halfb);
                ldsm4(Aq0, bb + off);
                ldsm4(Aq1, bb + 8192 + off);
            }
            uint32_t Bq0[2][4], Bq1[2][4];
#pragma unroll
            for (int nb = 0; nb < 2; nb++) {
                uint32_t offB = SWZ64((nb * 16 + r_lane) * 64 + kb + halfb);
                ldsm4(Bq0[nb], bb + 16384 + offB);
                ldsm4(Bq1[nb], bb + 18432 + offB);
            }
#pragma unroll
            for (int nb = 0; nb < 2; nb++)
#pragma unroll
                for (int e = 0; e < 2; e++) {
                    const int nf = nb * 2 + e;
                    imma(accH[nf], Aq0, Bq0[nb][e], Bq0[nb][2 + e]);
                    imma(accL[nf], Aq0, Bq1[nb][e], Bq1[nb][2 + e]);
                    imma(accL[nf], Aq1, Bq0[nb][e], Bq0[nb][2 + e]);
                }
        }
    }

    // epilogue: P = dequantized GEMM value (pre-s_h)
    const int g = lane >> 2, t4 = lane & 3;
#pragma unroll
    for (int nf = 0; nf < 4; nf++) {
        const int cl = nf * 8 + t4 * 2;
        const float swa = sw[c0 + cl] * INV127SQ, swb = sw[c0 + cl + 1] * INV127SQ;
#pragma unroll
        for (int h = 0; h < 2; h++) {
            const int row = m0 + warp_m * 16 + g + h * 8;
            float2 o;
            o.x = swa * ((float)accH[nf][h * 2 + 0] + INV128 * (float)accL[nf][h * 2 + 0]);
            o.y = swb * ((float)accH[nf][h * 2 + 1] + INV128 * (float)accL[nf][h * 2 + 1]);
            *(float2*)(P + (size_t)row * DOUT + c0 + cl) = o;
        }
    }
}

// ---------------- combine: out = P1*P2*S_H2 ----------------
__global__ void combine_kernel(float* __restrict__ out) {
    size_t i = (size_t)blockIdx.x * 256 + threadIdx.x;
    float4 a = ((const float4*)g_P1)[i];
    float4 b = ((const float4*)g_P2)[i];
    float4 o;
    o.x = a.x * b.x * S_H2;
    o.y = a.y * b.y * S_H2;
    o.z = a.z * b.z * S_H2;
    o.w = a.w * b.w * S_H2;
    ((float4*)out)[i] = o;
}

// ---------------- launch ----------------
// Inputs (metadata order): x, W_rff1, bias, W_rff2, W_sig1, W_sig2
extern "C" void kernel_launch(void* const* d_in, const int* in_sizes, int n_in,
                              void* d_out, int out_size)
{
    (void)in_sizes; (void)n_in; (void)out_size;
    const float* x    = (const float*)d_in[0];
    const float* W1   = (const float*)d_in[1];
    const float* bias = (const float*)d_in[2];
    const float* W2   = (const float*)d_in[3];
    const float* W3   = (const float*)d_in[4];
    const float* W4   = (const float*)d_in[5];
    float* out = (float*)d_out;

    cudaFuncSetAttribute(stage1_kernel, cudaFuncAttributeMaxDynamicSharedMemorySize, S1_SMEM);
    cudaFuncSetAttribute(stage2_kernel, cudaFuncAttributeMaxDynamicSharedMemorySize, S2_SMEM);

    quant_x_kernel<<<NROWS / 8, 256>>>(x);
    wcolmax13_kernel<<<dim3(HID / 256, 8, 2),  256>>>(W1, W3);
    wcolmax24_kernel<<<dim3(DOUT / 256, 8, 2), 256>>>(W2, W4);
    wquant13_kernel<<<dim3(DIN / 32, HID / 32, 2),  dim3(32, 8)>>>(W1, W3);
    wquant24_kernel<<<dim3(HID / 32, DOUT / 32, 2), dim3(32, 8)>>>(W2, W4);
    stage1_kernel<<<dim3(HID / 32, NROWS / 128, 2), 256, S1_SMEM>>>(bias);
    stage2_kernel<<<dim3(DOUT / 32, NROWS / 128, 2), 256, S2_SMEM>>>();
    combine_kernel<<<(NROWS * DOUT / 4) / 256, 256>>>(out);
}